// round 2
// baseline (speedup 1.0000x reference)
#include <cuda_runtime.h>
#include <cstdint>

// Problem constants (fixed by the reference: n=4096, d=2048, num_ids=256)
#define N_ROWS 4096
#define DCOLS  2048
#define ROW_F4 (DCOLS / 4)   // 512 float4 per row

// Scratch: gather indices for pair2. [0..4095] = idx_pos, [4096..8191] = idx_neg.
__device__ int g_idx[2 * N_ROWS];

// ---------------------------------------------------------------------------
// Bit-exact JAX threefry-2x32 (20 rounds), matching jax._src.prng.threefry2x32
// ---------------------------------------------------------------------------
__device__ __forceinline__ void threefry2x32(uint32_t k0, uint32_t k1,
                                             uint32_t c0, uint32_t c1,
                                             uint32_t& o0, uint32_t& o1) {
    const uint32_t ks2 = k0 ^ k1 ^ 0x1BD11BDAu;
    uint32_t x0 = c0 + k0;
    uint32_t x1 = c1 + k1;
#define TF_ROUND(r) { x0 += x1; x1 = (x1 << (r)) | (x1 >> (32 - (r))); x1 ^= x0; }
    TF_ROUND(13) TF_ROUND(15) TF_ROUND(26) TF_ROUND(6)
    x0 += k1;  x1 += ks2 + 1u;
    TF_ROUND(17) TF_ROUND(29) TF_ROUND(16) TF_ROUND(24)
    x0 += ks2; x1 += k0 + 2u;
    TF_ROUND(13) TF_ROUND(15) TF_ROUND(26) TF_ROUND(6)
    x0 += k0;  x1 += k1 + 3u;
    TF_ROUND(17) TF_ROUND(29) TF_ROUND(16) TF_ROUND(24)
    x0 += k1;  x1 += ks2 + 4u;
    TF_ROUND(13) TF_ROUND(15) TF_ROUND(26) TF_ROUND(6)
    x0 += ks2; x1 += k0 + 5u;
#undef TF_ROUND
    o0 = x0; o1 = x1;
}

// jax.random.uniform f32 bit conversion: bitcast(0x3F800000 | (bits >> 9)) - 1
__device__ __forceinline__ float bits_to_uniform(uint32_t b) {
    return __uint_as_float(0x3F800000u | (b >> 9)) - 1.0f;
}

// Partitionable threefry 32-bit random bits for element i of a flat array:
// counter = uint64(i) -> (hi=0, lo=i); output = o0 ^ o1.
// (jax/_src/prng.py::_threefry_random_bits_partitionable, default since 0.4.30)
__device__ __forceinline__ uint32_t jax_bits32(uint32_t key_lo, uint32_t i) {
    uint32_t o0, o1;
    threefry2x32(0u, key_lo, 0u, i, o0, o1);
    return o0 ^ o1;
}

// ---------------------------------------------------------------------------
// prep_kernel: histogram of targets -> pos/neg counts -> partitionable-threefry
// uniforms -> truncated-multiply indices (exactly matching the reference).
// Also writes y = [ones(n); zeros(n)]. One block, 256 threads.
// ---------------------------------------------------------------------------
__global__ void prep_kernel(const int* __restrict__ targets,
                            float* __restrict__ y_out) {
    __shared__ int hist[256];
    const int t = threadIdx.x;
    hist[t] = 0;
    __syncthreads();

    for (int i = t; i < N_ROWS; i += 256)
        atomicAdd(&hist[targets[i]], 1);
    __syncthreads();

    for (int i = t; i < N_ROWS; i += 256) {
        const float u = bits_to_uniform(jax_bits32(1u, (uint32_t)i)); // key(1)
        const float v = bits_to_uniform(jax_bits32(2u, (uint32_t)i)); // key(2)
        const int pc = hist[targets[i]];
        int       nc = N_ROWS - pc;
        if (nc < 1) nc = 1;
        int ip = (int)(u * (float)pc);    // f32 mul + trunc == astype(int32)
        if (ip > pc - 1) ip = pc - 1;
        int in2 = (int)(v * (float)nc);
        if (in2 > nc - 1) in2 = nc - 1;
        g_idx[i]          = ip;
        g_idx[N_ROWS + i] = in2;
    }

    // y = [1]*n ++ [0]*n
    for (int i = t; i < 2 * N_ROWS; i += 256)
        y_out[i] = (i < N_ROWS) ? 1.0f : 0.0f;
}

// ---------------------------------------------------------------------------
// copy_kernel: writes pair1 (2n x d) then pair2 (2n x d) as one flat float4
// range. pair1 row r copies inputs[r & 4095]; pair2 row r copies
// inputs[g_idx[r]]. 8192 blocks x 256 threads x 4 float4 = exact coverage.
// ---------------------------------------------------------------------------
__global__ void copy_kernel(const float4* __restrict__ in,
                            float4* __restrict__ out) {
    const unsigned P      = 2u * N_ROWS * ROW_F4;             // pair1 float4 count
    const unsigned total  = 2u * P;                           // pair1 + pair2
    const unsigned stride = gridDim.x * blockDim.x;
    unsigned g = blockIdx.x * blockDim.x + threadIdx.x;
#pragma unroll
    for (int it = 0; it < 4; ++it, g += stride) {
        if (g >= total) break;  // exact by construction; guard for safety
        unsigned r, col;
        int src;
        if (g < P) {
            r   = g >> 9;            // /512
            col = g & 511u;
            src = (int)(r & (N_ROWS - 1));      // row mod 4096
        } else {
            const unsigned g2 = g - P;
            r   = g2 >> 9;
            col = g2 & 511u;
            src = g_idx[r];                      // gather index
        }
        const float4 v = __ldg(in + (size_t)src * ROW_F4 + col);
        __stcs(out + g, v);   // streaming store: don't pollute L2 (keep inputs hot)
    }
}

// ---------------------------------------------------------------------------
// kernel_launch: inputs = d_in[0] (f32, 4096x2048), targets = d_in[1] (i32, 4096)
// out layout (flat f32): pair1 [2n*d] | pair2 [2n*d] | y [2n]
// ---------------------------------------------------------------------------
extern "C" void kernel_launch(void* const* d_in, const int* in_sizes, int n_in,
                              void* d_out, int out_size) {
    (void)in_sizes; (void)n_in; (void)out_size;
    const float* inputs  = (const float*)d_in[0];
    const int*   targets = (const int*)d_in[1];
    float*       out     = (float*)d_out;
    float*       y       = out + (size_t)4 * N_ROWS * DCOLS;  // after pair1|pair2

    prep_kernel<<<1, 256>>>(targets, y);
    copy_kernel<<<8192, 256>>>((const float4*)inputs, (float4*)out);
}

// round 5
// speedup vs baseline: 1.2516x; 1.2516x over previous
#include <cuda_runtime.h>
#include <cstdint>

// Problem constants (fixed by the reference: n=4096, d=2048, num_ids=256)
#define N_ROWS 4096
#define DCOLS  2048
#define ROW_F4 (DCOLS / 4)   // 512 float4 per row

// Scratch: gather indices for pair2. [0..4095] = idx_pos, [4096..8191] = idx_neg.
__device__ int g_idx[2 * N_ROWS];

// ---------------------------------------------------------------------------
// Bit-exact JAX threefry-2x32 (20 rounds)
// ---------------------------------------------------------------------------
__device__ __forceinline__ void threefry2x32(uint32_t k0, uint32_t k1,
                                             uint32_t c0, uint32_t c1,
                                             uint32_t& o0, uint32_t& o1) {
    const uint32_t ks2 = k0 ^ k1 ^ 0x1BD11BDAu;
    uint32_t x0 = c0 + k0;
    uint32_t x1 = c1 + k1;
#define TF_ROUND(r) { x0 += x1; x1 = (x1 << (r)) | (x1 >> (32 - (r))); x1 ^= x0; }
    TF_ROUND(13) TF_ROUND(15) TF_ROUND(26) TF_ROUND(6)
    x0 += k1;  x1 += ks2 + 1u;
    TF_ROUND(17) TF_ROUND(29) TF_ROUND(16) TF_ROUND(24)
    x0 += ks2; x1 += k0 + 2u;
    TF_ROUND(13) TF_ROUND(15) TF_ROUND(26) TF_ROUND(6)
    x0 += k0;  x1 += k1 + 3u;
    TF_ROUND(17) TF_ROUND(29) TF_ROUND(16) TF_ROUND(24)
    x0 += k1;  x1 += ks2 + 4u;
    TF_ROUND(13) TF_ROUND(15) TF_ROUND(26) TF_ROUND(6)
    x0 += ks2; x1 += k0 + 5u;
#undef TF_ROUND
    o0 = x0; o1 = x1;
}

// jax.random.uniform f32: bitcast(0x3F800000 | (bits >> 9)) - 1
__device__ __forceinline__ float bits_to_uniform(uint32_t b) {
    return __uint_as_float(0x3F800000u | (b >> 9)) - 1.0f;
}

// Partitionable threefry random bits for element i: counter=(0,i), out = o0^o1.
__device__ __forceinline__ uint32_t jax_bits32(uint32_t key_lo, uint32_t i) {
    uint32_t o0, o1;
    threefry2x32(0u, key_lo, 0u, i, o0, o1);
    return o0 ^ o1;
}

// ---------------------------------------------------------------------------
// prep_kernel: 16 blocks x 256 threads. Each block builds its own histogram
// (targets = 16KB, L2-hot) and computes 256 rows' indices (1 row/thread).
// Also writes y = [ones(n); zeros(n)], distributed across blocks.
// ---------------------------------------------------------------------------
#define PREP_BLOCKS 16
__global__ void prep_kernel(const int* __restrict__ targets,
                            float* __restrict__ y_out) {
    __shared__ int hist[256];
    const int t = threadIdx.x;
    const int b = blockIdx.x;
    hist[t] = 0;
    __syncthreads();

    // Redundant per-block histogram (cheap: 16 L2-hot loads + 16 smem atomics)
    #pragma unroll
    for (int k = 0; k < N_ROWS / 256; ++k)
        atomicAdd(&hist[targets[k * 256 + t]], 1);
    __syncthreads();

    // One row per thread: i in [b*256, b*256+256)
    {
        const int i = b * 256 + t;
        const float u = bits_to_uniform(jax_bits32(1u, (uint32_t)i)); // key(1)
        const float v = bits_to_uniform(jax_bits32(2u, (uint32_t)i)); // key(2)
        const int pc = hist[targets[i]];
        int       nc = N_ROWS - pc;
        if (nc < 1) nc = 1;
        int ip = (int)(u * (float)pc);    // f32 mul + trunc == astype(int32)
        if (ip > pc - 1) ip = pc - 1;
        int in2 = (int)(v * (float)nc);
        if (in2 > nc - 1) in2 = nc - 1;
        g_idx[i]          = ip;
        g_idx[N_ROWS + i] = in2;
    }

    // y = [1]*n ++ [0]*n ; block b writes chunk b of 2n/16 = 512 floats
    {
        const int base = b * (2 * N_ROWS / PREP_BLOCKS);
        #pragma unroll
        for (int k = 0; k < (2 * N_ROWS / PREP_BLOCKS) / 256; ++k) {
            const int i = base + k * 256 + t;
            y_out[i] = (i < N_ROWS) ? 1.0f : 0.0f;
        }
    }
}

// ---------------------------------------------------------------------------
// copy_kernel: blocked assignment, whole rows per block.
//   Blocks [0, 1024):    pair1. Block p owns input rows [p*4, p*4+4).
//       Each float4 is loaded ONCE and stored TWICE (out row r and r+4096).
//   Blocks [1024, 3072): pair2. Block q (q = blockIdx-1024, q in [0,2048))
//       owns pair2 rows [q*4, q*4+4) of 8192, gathering inputs[g_idx[row]].
// 256 threads; each thread handles float4s at stride 256 (coalesced).
// ---------------------------------------------------------------------------
#define P1_BLOCKS 1024
#define P2_BLOCKS 2048   // 8192 pair2 rows / 4 rows per block
__global__ void copy_kernel(const float4* __restrict__ in,
                            float4* __restrict__ out) {
    const int t = threadIdx.x;
    const int b = blockIdx.x;

    if (b < P1_BLOCKS) {
        // pair1: 4 input rows, dual store
        const int row0 = b * 4;
        #pragma unroll
        for (int rr = 0; rr < 4; ++rr) {
            const int r = row0 + rr;
            const float4* src  = in  + (size_t)r * ROW_F4;
            float4*       dstA = out + (size_t)r * ROW_F4;                 // pair1 row r
            float4*       dstB = out + (size_t)(r + N_ROWS) * ROW_F4;      // pair1 row r+n
            #pragma unroll
            for (int k = 0; k < ROW_F4 / 256; ++k) {   // 2 iters
                const int c = k * 256 + t;
                const float4 v = __ldg(src + c);
                __stcs(dstA + c, v);
                __stcs(dstB + c, v);
            }
        }
    } else {
        // pair2: 4 gathered rows
        const int q    = b - P1_BLOCKS;
        const int row0 = q * 4;                      // pair2 row in [0, 8192)
        float4* base = out + (size_t)2 * N_ROWS * ROW_F4;  // start of pair2
        #pragma unroll
        for (int rr = 0; rr < 4; ++rr) {
            const int r   = row0 + rr;
            const int src = __ldg(&g_idx[r]);
            const float4* s = in   + (size_t)src * ROW_F4;
            float4*       d = base + (size_t)r   * ROW_F4;
            #pragma unroll
            for (int k = 0; k < ROW_F4 / 256; ++k) {   // 2 iters
                const int c = k * 256 + t;
                __stcs(d + c, __ldg(s + c));
            }
        }
    }
}

// ---------------------------------------------------------------------------
// kernel_launch: inputs = d_in[0] (f32 4096x2048), targets = d_in[1] (i32 4096)
// out layout (flat f32): pair1 [2n*d] | pair2 [2n*d] | y [2n]
// ---------------------------------------------------------------------------
extern "C" void kernel_launch(void* const* d_in, const int* in_sizes, int n_in,
                              void* d_out, int out_size) {
    (void)in_sizes; (void)n_in; (void)out_size;
    const float* inputs  = (const float*)d_in[0];
    const int*   targets = (const int*)d_in[1];
    float*       out     = (float*)d_out;
    float*       y       = out + (size_t)4 * N_ROWS * DCOLS;  // after pair1|pair2

    prep_kernel<<<PREP_BLOCKS, 256>>>(targets, y);
    copy_kernel<<<P1_BLOCKS + P2_BLOCKS, 256>>>((const float4*)inputs, (float4*)out);
}

// round 6
// speedup vs baseline: 1.3304x; 1.0630x over previous
#include <cuda_runtime.h>
#include <cstdint>

// Problem constants (fixed by the reference: n=4096, d=2048, num_ids=256)
#define N_ROWS 4096
#define DCOLS  2048
#define ROW_F4 (DCOLS / 4)   // 512 float4 per row
#define P1_BLOCKS 1024       // pair1: 4096 input rows / 4 rows per block
#define P2_BLOCKS 2048       // pair2: 8192 rows / 4 rows per block

// ---------------------------------------------------------------------------
// Bit-exact JAX threefry-2x32 (20 rounds)
// ---------------------------------------------------------------------------
__device__ __forceinline__ void threefry2x32(uint32_t k0, uint32_t k1,
                                             uint32_t c0, uint32_t c1,
                                             uint32_t& o0, uint32_t& o1) {
    const uint32_t ks2 = k0 ^ k1 ^ 0x1BD11BDAu;
    uint32_t x0 = c0 + k0;
    uint32_t x1 = c1 + k1;
#define TF_ROUND(r) { x0 += x1; x1 = (x1 << (r)) | (x1 >> (32 - (r))); x1 ^= x0; }
    TF_ROUND(13) TF_ROUND(15) TF_ROUND(26) TF_ROUND(6)
    x0 += k1;  x1 += ks2 + 1u;
    TF_ROUND(17) TF_ROUND(29) TF_ROUND(16) TF_ROUND(24)
    x0 += ks2; x1 += k0 + 2u;
    TF_ROUND(13) TF_ROUND(15) TF_ROUND(26) TF_ROUND(6)
    x0 += k0;  x1 += k1 + 3u;
    TF_ROUND(17) TF_ROUND(29) TF_ROUND(16) TF_ROUND(24)
    x0 += k1;  x1 += ks2 + 4u;
    TF_ROUND(13) TF_ROUND(15) TF_ROUND(26) TF_ROUND(6)
    x0 += ks2; x1 += k0 + 5u;
#undef TF_ROUND
    o0 = x0; o1 = x1;
}

// jax.random.uniform f32: bitcast(0x3F800000 | (bits >> 9)) - 1
__device__ __forceinline__ float bits_to_uniform(uint32_t b) {
    return __uint_as_float(0x3F800000u | (b >> 9)) - 1.0f;
}

// Partitionable threefry random bits for element i: counter=(0,i), out = o0^o1.
__device__ __forceinline__ uint32_t jax_bits32(uint32_t key_lo, uint32_t i) {
    uint32_t o0, o1;
    threefry2x32(0u, key_lo, 0u, i, o0, o1);
    return o0 ^ o1;
}

// ---------------------------------------------------------------------------
// fused_kernel: single launch, no inter-block dependencies.
//   Blocks [0, 1024):    pair1. Block p owns input rows [p*4, p*4+4); each
//       float4 loaded once, stored to pair1 rows r and r+4096. First 16
//       blocks also write their 512-float chunk of y.
//   Blocks [1024, 3072): pair2. Block computes its 4 gather indices itself:
//       same-identity counts by direct comparison over targets (16 KB,
//       L2-hot), then partitionable-threefry uniforms -> truncated-multiply
//       indices; then gathers 4 rows.
// Loads batched 4-deep (2 rows x 2 cols) before stores for MLP.
// ---------------------------------------------------------------------------
__global__ void fused_kernel(const float4* __restrict__ in,
                             const int* __restrict__ targets,
                             float4* __restrict__ out,
                             float* __restrict__ y_out) {
    const int t = threadIdx.x;
    const int b = blockIdx.x;

    if (b < P1_BLOCKS) {
        // ---- pair1: dual store, batched loads ----
        const int row0 = b * 4;
        #pragma unroll
        for (int rp = 0; rp < 2; ++rp) {
            const int r0 = row0 + rp * 2;
            const int r1 = r0 + 1;
            const float4* s0 = in + (size_t)r0 * ROW_F4;
            const float4* s1 = in + (size_t)r1 * ROW_F4;
            const float4 a0 = __ldg(s0 + t);
            const float4 a1 = __ldg(s0 + t + 256);
            const float4 b0 = __ldg(s1 + t);
            const float4 b1 = __ldg(s1 + t + 256);
            float4* dA0 = out + (size_t)r0 * ROW_F4;
            float4* dB0 = out + (size_t)(r0 + N_ROWS) * ROW_F4;
            float4* dA1 = out + (size_t)r1 * ROW_F4;
            float4* dB1 = out + (size_t)(r1 + N_ROWS) * ROW_F4;
            __stcs(dA0 + t,       a0); __stcs(dA0 + t + 256, a1);
            __stcs(dB0 + t,       a0); __stcs(dB0 + t + 256, a1);
            __stcs(dA1 + t,       b0); __stcs(dA1 + t + 256, b1);
            __stcs(dB1 + t,       b0); __stcs(dB1 + t + 256, b1);
        }
        // y = [1]*n ++ [0]*n, 512 floats per block for the first 16 blocks
        if (b < 16) {
            const int base = b * 512;
            y_out[base + t]       = (base + t       < N_ROWS) ? 1.0f : 0.0f;
            y_out[base + 256 + t] = (base + 256 + t < N_ROWS) ? 1.0f : 0.0f;
        }
    } else {
        // ---- pair2: in-block index computation, then gather ----
        const int q    = b - P1_BLOCKS;
        const int row0 = q * 4;                 // pair2 row in [0, 8192)

        __shared__ int s_tgt[4];
        __shared__ int s_cnt[4];
        __shared__ int s_src[4];
        if (t < 4) {
            s_tgt[t] = targets[(row0 + t) & (N_ROWS - 1)];
            s_cnt[t] = 0;
        }
        __syncthreads();

        // Count targets[j] == tgt_r for each of the 4 rows (== hist[tgt])
        const int t0 = s_tgt[0], t1 = s_tgt[1], t2 = s_tgt[2], t3 = s_tgt[3];
        int c0 = 0, c1 = 0, c2 = 0, c3 = 0;
        #pragma unroll
        for (int k = 0; k < N_ROWS / 256; ++k) {       // 16 L2-hot loads
            const int v = __ldg(&targets[k * 256 + t]);
            c0 += (v == t0); c1 += (v == t1); c2 += (v == t2); c3 += (v == t3);
        }
        #pragma unroll
        for (int off = 16; off; off >>= 1) {
            c0 += __shfl_down_sync(0xFFFFFFFFu, c0, off);
            c1 += __shfl_down_sync(0xFFFFFFFFu, c1, off);
            c2 += __shfl_down_sync(0xFFFFFFFFu, c2, off);
            c3 += __shfl_down_sync(0xFFFFFFFFu, c3, off);
        }
        if ((t & 31) == 0) {
            atomicAdd(&s_cnt[0], c0); atomicAdd(&s_cnt[1], c1);
            atomicAdd(&s_cnt[2], c2); atomicAdd(&s_cnt[3], c3);
        }
        __syncthreads();

        if (t < 4) {
            const int r  = row0 + t;
            const int i  = r & (N_ROWS - 1);           // element index for PRNG
            const int pc = s_cnt[t];
            int      cnt;
            uint32_t key;
            if (r < N_ROWS) { cnt = pc; key = 1u; }    // positives: key(1)
            else {                                      // negatives: key(2)
                cnt = N_ROWS - pc;
                if (cnt < 1) cnt = 1;
                key = 2u;
            }
            const float u = bits_to_uniform(jax_bits32(key, (uint32_t)i));
            int idx = (int)(u * (float)cnt);           // f32 mul + trunc
            if (idx > cnt - 1) idx = cnt - 1;
            s_src[t] = idx;
        }
        __syncthreads();

        float4* base = out + (size_t)2 * N_ROWS * ROW_F4;  // start of pair2
        #pragma unroll
        for (int rp = 0; rp < 2; ++rp) {
            const int r0 = row0 + rp * 2;
            const int r1 = r0 + 1;
            const float4* sA = in + (size_t)s_src[rp * 2]     * ROW_F4;
            const float4* sB = in + (size_t)s_src[rp * 2 + 1] * ROW_F4;
            const float4 a0 = __ldg(sA + t);
            const float4 a1 = __ldg(sA + t + 256);
            const float4 b0 = __ldg(sB + t);
            const float4 b1 = __ldg(sB + t + 256);
            float4* d0 = base + (size_t)r0 * ROW_F4;
            float4* d1 = base + (size_t)r1 * ROW_F4;
            __stcs(d0 + t,       a0); __stcs(d0 + t + 256, a1);
            __stcs(d1 + t,       b0); __stcs(d1 + t + 256, b1);
        }
    }
}

// ---------------------------------------------------------------------------
// kernel_launch: inputs = d_in[0] (f32 4096x2048), targets = d_in[1] (i32 4096)
// out layout (flat f32): pair1 [2n*d] | pair2 [2n*d] | y [2n]
// ---------------------------------------------------------------------------
extern "C" void kernel_launch(void* const* d_in, const int* in_sizes, int n_in,
                              void* d_out, int out_size) {
    (void)in_sizes; (void)n_in; (void)out_size;
    const float* inputs  = (const float*)d_in[0];
    const int*   targets = (const int*)d_in[1];
    float*       out     = (float*)d_out;
    float*       y       = out + (size_t)4 * N_ROWS * DCOLS;  // after pair1|pair2

    fused_kernel<<<P1_BLOCKS + P2_BLOCKS, 256>>>(
        (const float4*)inputs, targets, (float4*)out, y);
}